// round 1
// baseline (speedup 1.0000x reference)
#include <cuda_runtime.h>
#include <cuda_bf16.h>
#include <cstdint>

// Problem constants (verified against reference setup_inputs):
//   B = 64, D = 32, L = 8192
// out layout assumed: [out (B*D*L f32)] then [mask (B*D*L f32, 0.0/1.0)]

#define D_DIM 32
#define MAX_ROWS 4096

// Per-(b,d) zone metadata: x = start, y = len
__device__ int2 g_meta[MAX_ROWS];

// ---------------------------------------------------------------------------
// Kernel 1: compute exclusive prefix sums of schemas rows.
// schemas may be int64 or int32 on disk (JAX x64 ambiguity) — detect at
// runtime: for int64 with values in [0,256), every odd 32-bit word is 0.
// ---------------------------------------------------------------------------
__global__ void meta_kernel(const unsigned int* __restrict__ schemas_w,
                            int n_rows /* = B*D */) {
    int b = blockIdx.x * blockDim.x + threadIdx.x;   // batch index
    int B = n_rows / D_DIM;
    if (b >= B) return;

    // dtype detection on first 32 elements (64 words if int64)
    bool is64 = true;
    #pragma unroll 8
    for (int w = 1; w < 64; w += 2) {
        if (schemas_w[w] != 0u) { is64 = false; break; }
    }

    int start = 0;
    #pragma unroll
    for (int d = 0; d < D_DIM; d++) {
        int idx = b * D_DIM + d;
        unsigned int v = is64 ? schemas_w[2 * idx] : schemas_w[idx];
        g_meta[idx] = make_int2(start, (int)v);
        start += (int)v;
    }
}

// ---------------------------------------------------------------------------
// Kernel 2: fill out + mask. One CTA per (b,d) row. float4 stores.
// ---------------------------------------------------------------------------
__global__ void __launch_bounds__(256)
fill_kernel(const float* __restrict__ logits,
            float* __restrict__ out,
            int n_rows, int L) {
    int row = blockIdx.x;                 // b*D + d
    int b   = row / D_DIM;
    int2 m  = g_meta[row];
    int start = m.x;
    int len   = m.y;

    const float* __restrict__ lrow = logits + (long long)b * L;
    float4* __restrict__ orow = reinterpret_cast<float4*>(out + (long long)row * L);
    float4* __restrict__ mrow = reinterpret_cast<float4*>(
        out + (long long)n_rows * L + (long long)row * L);

    const float4 z4 = make_float4(0.f, 0.f, 0.f, 0.f);
    const float4 o4 = make_float4(1.f, 1.f, 1.f, 1.f);

    int nvec = L >> 2;                    // 2048
    for (int v = threadIdx.x; v < nvec; v += blockDim.x) {
        int j = v << 2;
        if (j >= len) {
            // bulk zero-fill path (~98.5% of all vectors)
            orow[v] = z4;
            mrow[v] = z4;
        } else if (j + 3 < len) {
            // fully-inside gather (unaligned source -> scalar loads)
            float4 val;
            val.x = lrow[start + j + 0];
            val.y = lrow[start + j + 1];
            val.z = lrow[start + j + 2];
            val.w = lrow[start + j + 3];
            orow[v] = val;
            mrow[v] = o4;
        } else {
            // boundary vector (at most 1 per row)
            float4 val = z4, mk = z4;
            if (j + 0 < len) { val.x = lrow[start + j + 0]; mk.x = 1.f; }
            if (j + 1 < len) { val.y = lrow[start + j + 1]; mk.y = 1.f; }
            if (j + 2 < len) { val.z = lrow[start + j + 2]; mk.z = 1.f; }
            orow[v] = val;
            mrow[v] = mk;
        }
    }
}

// ---------------------------------------------------------------------------
extern "C" void kernel_launch(void* const* d_in, const int* in_sizes, int n_in,
                              void* d_out, int out_size) {
    const unsigned int* schemas_w = (const unsigned int*)d_in[0];
    const float*        logits    = (const float*)d_in[1];
    float*              out       = (float*)d_out;

    int n_rows = in_sizes[0];             // B*D = 2048
    int B      = n_rows / D_DIM;          // 64
    int L      = in_sizes[1] / B;         // 8192

    meta_kernel<<<(B + 63) / 64, 64>>>(schemas_w, n_rows);
    fill_kernel<<<n_rows, 256>>>(logits, out, n_rows, L);
}

// round 4
// speedup vs baseline: 1.1657x; 1.1657x over previous
#include <cuda_runtime.h>
#include <cuda_bf16.h>
#include <cstdint>

// LogitSeparator: out[b,d,j] = logits[b, start(b,d)+j] for j < len(b,d) else 0
//                 mask[b,d,j] = (j < len) ? 1.0 : 0.0
// where start = exclusive cumsum of schemas[b,:] at d, len = schemas[b,d].
// Output layout: [out (B*D*L f32)] ++ [mask (B*D*L f32)], verified R1 (rel_err 0).
//
// Single fused kernel: each CTA owns one (b,d) row; warp 0 computes
// (start,len) via shfl prefix-scan, then all threads stream float4 stores.

#define D_DIM 32

__global__ void __launch_bounds__(512)
fused_fill_kernel(const unsigned int* __restrict__ schemas_w,
                  const float* __restrict__ logits,
                  float* __restrict__ out,
                  int n_rows, int L) {
    int row = blockIdx.x;                 // b*D + d
    int b   = row >> 5;                   // D_DIM == 32
    int d   = row & (D_DIM - 1);

    __shared__ int s_start, s_len;

    if (threadIdx.x < 32) {
        int lane = threadIdx.x;
        // dtype detection: int64 schemas in [0,256) -> every odd 32-bit word
        // of the first 32 elements is zero. Each lane checks one odd word of
        // the first schema row (indices 1,3,...,63 — in-bounds for both dtypes
        // since the buffer holds >= 2048 32-bit words either way).
        unsigned int oddw = schemas_w[2 * lane + 1];
        bool is64 = (__ballot_sync(0xffffffffu, oddw != 0u) == 0u);

        int base = b * D_DIM;
        unsigned int v = is64 ? schemas_w[2 * (base + lane)]
                              : schemas_w[base + lane];
        // inclusive prefix scan over the 32 schema entries of this batch row
        int x = (int)v;
        #pragma unroll
        for (int o = 1; o < 32; o <<= 1) {
            int y = __shfl_up_sync(0xffffffffu, x, o);
            if (lane >= o) x += y;
        }
        if (lane == d) { s_start = x - (int)v; s_len = (int)v; }
    }
    __syncthreads();

    int start = s_start;
    int len   = s_len;

    const float* __restrict__ lrow = logits + (long long)b * L;
    float4* __restrict__ orow = reinterpret_cast<float4*>(out + (long long)row * L);
    float4* __restrict__ mrow = reinterpret_cast<float4*>(
        out + (long long)n_rows * L + (long long)row * L);

    const float4 z4 = make_float4(0.f, 0.f, 0.f, 0.f);
    const float4 o4 = make_float4(1.f, 1.f, 1.f, 1.f);

    int nvec = L >> 2;                    // 2048 float4 per row half
    for (int v = threadIdx.x; v < nvec; v += blockDim.x) {
        int j = v << 2;
        if (j >= len) {
            // bulk zero-fill (~98.5% of vectors)
            orow[v] = z4;
            mrow[v] = z4;
        } else if (j + 3 < len) {
            float4 val;
            val.x = lrow[start + j + 0];
            val.y = lrow[start + j + 1];
            val.z = lrow[start + j + 2];
            val.w = lrow[start + j + 3];
            orow[v] = val;
            mrow[v] = o4;
        } else {
            // boundary vector (at most 1 per row)
            float4 val = z4, mk = z4;
            if (j + 0 < len) { val.x = lrow[start + j + 0]; mk.x = 1.f; }
            if (j + 1 < len) { val.y = lrow[start + j + 1]; mk.y = 1.f; }
            if (j + 2 < len) { val.z = lrow[start + j + 2]; mk.z = 1.f; }
            orow[v] = val;
            mrow[v] = mk;
        }
    }
}

extern "C" void kernel_launch(void* const* d_in, const int* in_sizes, int n_in,
                              void* d_out, int out_size) {
    const unsigned int* schemas_w = (const unsigned int*)d_in[0];
    const float*        logits    = (const float*)d_in[1];
    float*              out       = (float*)d_out;

    int n_rows = in_sizes[0];             // B*D = 2048
    int B      = n_rows / D_DIM;          // 64
    int L      = in_sizes[1] / B;         // 8192

    fused_fill_kernel<<<n_rows, 512>>>(schemas_w, logits, out, n_rows, L);
}